// round 16
// baseline (speedup 1.0000x reference)
#include <cuda_runtime.h>

// entmax-1.5 over rows. zbuf holds z = (mask? s : -1e4)*0.5 (unshifted) in shared;
// active iff z > thr = rmax-1; tau = root of sum max((z-rmax)-tau,0)^2 = 1 in [-1,0];
// p = max(z-(rmax+tau),0)^2. Warp 0 solves: 10 bisections over <=128 register
// actives + exact fixed-support closed form tau = (S1-sqrt(S1^2-k(S2-1)))/k.
//
// R16 = R15 + EARLY ZERO-STORES: since tau >= -1, taup >= thr, so every element
// with z <= thr has p = 0 exactly, independent of tau. Those output chunks
// (~96.5%) are streamed to GMEM during the compact phase — overlapping the
// solve — and only chunks containing an active (~0.14/thread) are deferred.
// Post-solve tail: ~25x less shared re-read + store work.

constexpr int COLS    = 4096;
constexpr int THREADS = 256;
constexpr int PER     = COLS / THREADS;  // 16
constexpr int VEC     = PER / 4;         // 4
constexpr int NWARP   = THREADS / 32;    // 8
constexpr int NB      = 10;              // bisection iterations
constexpr int CAP     = 128;             // register fast path (4/lane)
constexpr int ACAP    = 1024;            // abuf capacity (mid path)

__device__ __forceinline__ float warp_sum(float v) {
#pragma unroll
    for (int off = 16; off > 0; off >>= 1)
        v += __shfl_xor_sync(0xffffffffu, v, off);
    return v;
}

__global__ __launch_bounds__(THREADS, 8) void entmax15_kernel(
    const float* __restrict__ scores,
    const int* __restrict__ mask,
    float* __restrict__ out)
{
    __shared__ float zbuf[COLS];     // full row of z (unshifted)
    __shared__ float abuf[ACAP];     // compacted actives (v = z - rmax)
    __shared__ float sh_max[NWARP];
    __shared__ float sh_tau;
    __shared__ int   cnt;

    const size_t row = blockIdx.x;
    const float* s = scores + row * COLS;
    const int*   m = mask   + row * COLS;
    float* o = out + row * COLS;

    const int t    = threadIdx.x;
    const int wid  = t >> 5;
    const int lane = t & 31;

    // ---- Load, mask, *0.5 -> shared; track local max ----
    float lmax = -3.402823e38f;
#pragma unroll
    for (int c = 0; c < VEC; ++c) {
        const int idx = c * (THREADS * 4) + t * 4;
        float4 v  = __ldcs(reinterpret_cast<const float4*>(s + idx));
        int4   mm = __ldcs(reinterpret_cast<const int4*>(m + idx));
        float4 zz;
        zz.x = (mm.x ? v.x : -1.0e4f) * 0.5f;
        zz.y = (mm.y ? v.y : -1.0e4f) * 0.5f;
        zz.z = (mm.z ? v.z : -1.0e4f) * 0.5f;
        zz.w = (mm.w ? v.w : -1.0e4f) * 0.5f;
        *reinterpret_cast<float4*>(zbuf + idx) = zz;
        lmax = fmaxf(lmax, fmaxf(fmaxf(zz.x, zz.y), fmaxf(zz.z, zz.w)));
    }
    const float tmax = lmax;         // private 16-element max

    // ---- Block max ----
#pragma unroll
    for (int off = 16; off > 0; off >>= 1)
        lmax = fmaxf(lmax, __shfl_xor_sync(0xffffffffu, lmax, off));
    if (lane == 0) sh_max[wid] = lmax;
    if (t == 0) cnt = 0;
    __syncthreads();
    float rmax = sh_max[0];
#pragma unroll
    for (int i = 1; i < NWARP; ++i) rmax = fmaxf(rmax, sh_max[i]);
    const float thr = rmax - 1.0f;   // active iff z > thr; z <= thr -> p = 0 exactly

    // ---- Compact + EARLY ZERO-STORES ----
    // Chunks with no element above thr are all-zero in the output regardless
    // of tau (taup = rmax + tau >= thr): stream them to GMEM now. Chunks with
    // an active are deferred (bitmask) until tau is known.
    const float4 zero4 = make_float4(0.0f, 0.0f, 0.0f, 0.0f);
    int defer = 0;
    if (tmax > thr) {
#pragma unroll
        for (int c = 0; c < VEC; ++c) {
            const int idx = c * (THREADS * 4) + t * 4;
            float4 zz = *reinterpret_cast<const float4*>(zbuf + idx);
            float cmax = fmaxf(fmaxf(zz.x, zz.y), fmaxf(zz.z, zz.w));
            if (cmax > thr) {
                defer |= (1 << c);
#pragma unroll
                for (int j = 0; j < 4; ++j) {
                    float zv = (&zz.x)[j];
                    if (zv > thr) {
                        int p = atomicAdd(&cnt, 1);      // warp-aggregated
                        if (p < ACAP) abuf[p] = zv - rmax;
                    }
                }
            } else {
                __stcs(reinterpret_cast<float4*>(o + idx), zero4);
            }
        }
    } else {
        // whole slice below threshold: 4 zero chunks, no shared re-read
#pragma unroll
        for (int c = 0; c < VEC; ++c) {
            const int idx = c * (THREADS * 4) + t * 4;
            __stcs(reinterpret_cast<float4*>(o + idx), zero4);
        }
    }
    __syncthreads();

    // ---- Warp 0 solves tau; others wait at the barrier below ----
    if (wid == 0) {
        const int n = cnt;   // >= 1 (max element has v = 0 > -1)
        float lo = -1.0f, hi = 0.0f;
        float tau;

        if (n <= CAP) {
            float v[4];
#pragma unroll
            for (int j = 0; j < 4; ++j) {
                int i = lane + 32 * j;
                v[j] = (i < n) ? abuf[i] : -2.0f;    // sentinel: never in support
            }
#pragma unroll 1
            for (int it = 0; it < NB; ++it) {
                const float tm = 0.5f * (lo + hi);
                float acc = 0.0f;
#pragma unroll
                for (int j = 0; j < 4; ++j) {
                    float d = fmaxf(v[j] - tm, 0.0f);
                    acc = fmaf(d, d, acc);
                }
                if (warp_sum(acc) >= 1.0f) lo = tm; else hi = tm;
            }
            float k = 0.0f, S1 = 0.0f, S2 = 0.0f;
#pragma unroll
            for (int j = 0; j < 4; ++j)
                if (v[j] > lo) { k += 1.0f; S1 += v[j]; S2 = fmaf(v[j], v[j], S2); }
            k = warp_sum(k); S1 = warp_sum(S1); S2 = warp_sum(S2);
            float disc = fmaxf(fmaf(S1, S1, -k * (S2 - 1.0f)), 0.0f);
            tau = (S1 - sqrtf(disc)) / k;
        } else if (n <= ACAP) {
#pragma unroll 1
            for (int it = 0; it < NB; ++it) {
                const float tm = 0.5f * (lo + hi);
                float acc = 0.0f;
                for (int i = lane; i < n; i += 32) {
                    float d = fmaxf(abuf[i] - tm, 0.0f);
                    acc = fmaf(d, d, acc);
                }
                if (warp_sum(acc) >= 1.0f) lo = tm; else hi = tm;
            }
            float k = 0.0f, S1 = 0.0f, S2 = 0.0f;
            for (int i = lane; i < n; i += 32) {
                float v = abuf[i];
                if (v > lo) { k += 1.0f; S1 += v; S2 = fmaf(v, v, S2); }
            }
            k = warp_sum(k); S1 = warp_sum(S1); S2 = warp_sum(S2);
            float disc = fmaxf(fmaf(S1, S1, -k * (S2 - 1.0f)), 0.0f);
            tau = (S1 - sqrtf(disc)) / k;
        } else {
            // pathological: scan the full row in shared (tau still in [-1,0],
            // so the early zero-stores remain exact)
#pragma unroll 1
            for (int it = 0; it < NB; ++it) {
                const float tm = 0.5f * (lo + hi);
                float acc = 0.0f;
                for (int i = lane; i < COLS; i += 32) {
                    float d = fmaxf((zbuf[i] - rmax) - tm, 0.0f);
                    acc = fmaf(d, d, acc);
                }
                if (warp_sum(acc) >= 1.0f) lo = tm; else hi = tm;
            }
            float k = 0.0f, S1 = 0.0f, S2 = 0.0f;
            for (int i = lane; i < COLS; i += 32) {
                float v = zbuf[i] - rmax;
                if (v > lo) { k += 1.0f; S1 += v; S2 = fmaf(v, v, S2); }
            }
            k = warp_sum(k); S1 = warp_sum(S1); S2 = warp_sum(S2);
            float disc = fmaxf(fmaf(S1, S1, -k * (S2 - 1.0f)), 0.0f);
            tau = (S1 - sqrtf(disc)) / k;
        }
        if (lane == 0) sh_tau = tau;
    }
    __syncthreads();

    // ---- Store only DEFERRED chunks (those containing actives) ----
    if (defer) {
        const float taup = sh_tau + rmax;    // p = max(z - taup, 0)^2
#pragma unroll
        for (int c = 0; c < VEC; ++c) {
            if (defer & (1 << c)) {
                const int idx = c * (THREADS * 4) + t * 4;
                float4 zz = *reinterpret_cast<const float4*>(zbuf + idx);
                float d0 = fmaxf(zz.x - taup, 0.0f);
                float d1 = fmaxf(zz.y - taup, 0.0f);
                float d2 = fmaxf(zz.z - taup, 0.0f);
                float d3 = fmaxf(zz.w - taup, 0.0f);
                float4 p;
                p.x = d0*d0; p.y = d1*d1; p.z = d2*d2; p.w = d3*d3;
                __stcs(reinterpret_cast<float4*>(o + idx), p);
            }
        }
    }
}

extern "C" void kernel_launch(void* const* d_in, const int* in_sizes, int n_in,
                              void* d_out, int out_size) {
    const float* scores = (const float*)d_in[0];
    const int*   mask   = (const int*)d_in[1];
    float* out = (float*)d_out;
    const int rows = in_sizes[0] / COLS;
    entmax15_kernel<<<rows, THREADS>>>(scores, mask, out);
}

// round 17
// speedup vs baseline: 1.0516x; 1.0516x over previous
#include <cuda_runtime.h>

// entmax-1.5 over rows. zbuf holds RAW masked scores y = (mask? s : -1e4)
// (the *0.5 is folded out of the hot load loop): z = y/2, rmax = ymax/2.
// Active iff z > rmax-1  <=>  y > ymax-2. tau = root of
// sum max((z-rmax)-tau,0)^2 = 1 in [-1,0]; p = max(y*0.5 - taup, 0)^2 with
// taup = rmax + tau. Warp 0 solves: 10 bisections over <=128 register-resident
// actives + exact fixed-support closed form tau = (S1-sqrt(S1^2-k(S2-1)))/k.
//
// R17 = R15 (best: 77.2us) with the load phase trimmed: 16 FMULs/thread moved
// out of the critical load burst (applied per-active in compact and per-element
// as FFMA in the already-hidden store phase). Same 32-reg / 8-CTA / 94%-occ
// envelope; per-thread tmax skip in compact preserved.

constexpr int COLS    = 4096;
constexpr int THREADS = 256;
constexpr int PER     = COLS / THREADS;  // 16
constexpr int VEC     = PER / 4;         // 4
constexpr int NWARP   = THREADS / 32;    // 8
constexpr int NB      = 10;              // bisection iterations
constexpr int CAP     = 128;             // register fast path (4/lane)
constexpr int ACAP    = 1024;            // abuf capacity (mid path)

__device__ __forceinline__ float warp_sum(float v) {
#pragma unroll
    for (int off = 16; off > 0; off >>= 1)
        v += __shfl_xor_sync(0xffffffffu, v, off);
    return v;
}

__global__ __launch_bounds__(THREADS, 8) void entmax15_kernel(
    const float* __restrict__ scores,
    const int* __restrict__ mask,
    float* __restrict__ out)
{
    __shared__ float zbuf[COLS];     // full row of RAW masked scores y
    __shared__ float abuf[ACAP];     // compacted actives (v = (y - ymax)*0.5)
    __shared__ float sh_max[NWARP];
    __shared__ float sh_tau;
    __shared__ int   cnt;

    const size_t row = blockIdx.x;
    const float* s = scores + row * COLS;
    const int*   m = mask   + row * COLS;
    float* o = out + row * COLS;

    const int t    = threadIdx.x;
    const int wid  = t >> 5;
    const int lane = t & 31;

    // ---- Load, mask -> shared (no scaling); track local max of y ----
    float lmax = -3.402823e38f;
#pragma unroll
    for (int c = 0; c < VEC; ++c) {
        const int idx = c * (THREADS * 4) + t * 4;
        float4 v  = __ldcs(reinterpret_cast<const float4*>(s + idx));
        int4   mm = __ldcs(reinterpret_cast<const int4*>(m + idx));
        float4 yy;
        yy.x = mm.x ? v.x : -1.0e4f;
        yy.y = mm.y ? v.y : -1.0e4f;
        yy.z = mm.z ? v.z : -1.0e4f;
        yy.w = mm.w ? v.w : -1.0e4f;
        *reinterpret_cast<float4*>(zbuf + idx) = yy;
        lmax = fmaxf(lmax, fmaxf(fmaxf(yy.x, yy.y), fmaxf(yy.z, yy.w)));
    }
    const float tmax = lmax;         // private 16-element max of y (skip test)

    // ---- Block max of y ----
#pragma unroll
    for (int off = 16; off > 0; off >>= 1)
        lmax = fmaxf(lmax, __shfl_xor_sync(0xffffffffu, lmax, off));
    if (lane == 0) sh_max[wid] = lmax;
    if (t == 0) cnt = 0;
    __syncthreads();
    float ymax = sh_max[0];
#pragma unroll
    for (int i = 1; i < NWARP; ++i) ymax = fmaxf(ymax, sh_max[i]);
    const float thr = ymax - 2.0f;   // active iff y > ymax-2 (<=> z > rmax-1)

    // ---- Compact actives from shared (store v = (y - ymax)*0.5) ----
    // Skip entirely if this thread's slice max can't exceed the threshold.
    if (tmax > thr) {
#pragma unroll
        for (int c = 0; c < VEC; ++c) {
            const int idx = c * (THREADS * 4) + t * 4;
            float4 yy = *reinterpret_cast<const float4*>(zbuf + idx);
#pragma unroll
            for (int j = 0; j < 4; ++j) {
                float yv = (&yy.x)[j];
                if (yv > thr) {
                    int p = atomicAdd(&cnt, 1);          // warp-aggregated
                    if (p < ACAP) abuf[p] = (yv - ymax) * 0.5f;
                }
            }
        }
    }
    __syncthreads();

    const float rmax = ymax * 0.5f;

    // ---- Warp 0 solves tau; others wait at the barrier below ----
    if (wid == 0) {
        const int n = cnt;   // >= 1 (max element has v = 0 > -1)
        float lo = -1.0f, hi = 0.0f;
        float tau;

        if (n <= CAP) {
            float v[4];
#pragma unroll
            for (int j = 0; j < 4; ++j) {
                int i = lane + 32 * j;
                v[j] = (i < n) ? abuf[i] : -2.0f;    // sentinel: never in support
            }
#pragma unroll 1
            for (int it = 0; it < NB; ++it) {
                const float tm = 0.5f * (lo + hi);
                float acc = 0.0f;
#pragma unroll
                for (int j = 0; j < 4; ++j) {
                    float d = fmaxf(v[j] - tm, 0.0f);
                    acc = fmaf(d, d, acc);
                }
                if (warp_sum(acc) >= 1.0f) lo = tm; else hi = tm;
            }
            float k = 0.0f, S1 = 0.0f, S2 = 0.0f;
#pragma unroll
            for (int j = 0; j < 4; ++j)
                if (v[j] > lo) { k += 1.0f; S1 += v[j]; S2 = fmaf(v[j], v[j], S2); }
            k = warp_sum(k); S1 = warp_sum(S1); S2 = warp_sum(S2);
            float disc = fmaxf(fmaf(S1, S1, -k * (S2 - 1.0f)), 0.0f);
            tau = (S1 - sqrtf(disc)) / k;
        } else if (n <= ACAP) {
#pragma unroll 1
            for (int it = 0; it < NB; ++it) {
                const float tm = 0.5f * (lo + hi);
                float acc = 0.0f;
                for (int i = lane; i < n; i += 32) {
                    float d = fmaxf(abuf[i] - tm, 0.0f);
                    acc = fmaf(d, d, acc);
                }
                if (warp_sum(acc) >= 1.0f) lo = tm; else hi = tm;
            }
            float k = 0.0f, S1 = 0.0f, S2 = 0.0f;
            for (int i = lane; i < n; i += 32) {
                float v = abuf[i];
                if (v > lo) { k += 1.0f; S1 += v; S2 = fmaf(v, v, S2); }
            }
            k = warp_sum(k); S1 = warp_sum(S1); S2 = warp_sum(S2);
            float disc = fmaxf(fmaf(S1, S1, -k * (S2 - 1.0f)), 0.0f);
            tau = (S1 - sqrtf(disc)) / k;
        } else {
            // pathological: scan the full row in shared (y -> v on the fly)
#pragma unroll 1
            for (int it = 0; it < NB; ++it) {
                const float tm = 0.5f * (lo + hi);
                float acc = 0.0f;
                for (int i = lane; i < COLS; i += 32) {
                    float vv = (zbuf[i] - ymax) * 0.5f;
                    float d = fmaxf(vv - tm, 0.0f);
                    acc = fmaf(d, d, acc);
                }
                if (warp_sum(acc) >= 1.0f) lo = tm; else hi = tm;
            }
            float k = 0.0f, S1 = 0.0f, S2 = 0.0f;
            for (int i = lane; i < COLS; i += 32) {
                float vv = (zbuf[i] - ymax) * 0.5f;
                if (vv > lo) { k += 1.0f; S1 += vv; S2 = fmaf(vv, vv, S2); }
            }
            k = warp_sum(k); S1 = warp_sum(S1); S2 = warp_sum(S2);
            float disc = fmaxf(fmaf(S1, S1, -k * (S2 - 1.0f)), 0.0f);
            tau = (S1 - sqrtf(disc)) / k;
        }
        if (lane == 0) sh_tau = tau;
    }
    __syncthreads();
    const float taup = sh_tau + rmax;    // p = max(y*0.5 - taup, 0)^2

    // ---- Store p from shared (FFMA folds the deferred *0.5) ----
#pragma unroll
    for (int c = 0; c < VEC; ++c) {
        const int idx = c * (THREADS * 4) + t * 4;
        float4 yy = *reinterpret_cast<const float4*>(zbuf + idx);
        float d0 = fmaxf(fmaf(yy.x, 0.5f, -taup), 0.0f);
        float d1 = fmaxf(fmaf(yy.y, 0.5f, -taup), 0.0f);
        float d2 = fmaxf(fmaf(yy.z, 0.5f, -taup), 0.0f);
        float d3 = fmaxf(fmaf(yy.w, 0.5f, -taup), 0.0f);
        float4 p;
        p.x = d0*d0; p.y = d1*d1; p.z = d2*d2; p.w = d3*d3;
        __stcs(reinterpret_cast<float4*>(o + idx), p);
    }
}

extern "C" void kernel_launch(void* const* d_in, const int* in_sizes, int n_in,
                              void* d_out, int out_size) {
    const float* scores = (const float*)d_in[0];
    const int*   mask   = (const int*)d_in[1];
    float* out = (float*)d_out;
    const int rows = in_sizes[0] / COLS;
    entmax15_kernel<<<rows, THREADS>>>(scores, mask, out);
}